// round 14
// baseline (speedup 1.0000x reference)
#include <cuda_runtime.h>
#include <cuda_fp8.h>
#include <cstdint>

#define BSZ 4096
#define D 128
#define TWO_B 8192
#define NRB 64
#define NTHREADS 256
#define NCTAS 148

// fp8 tile row: 128 B data + 16 B pad = 144 B (4r mod 32 banking -> conflict-free)
#define LDS_BYTES 144
#define TILE_BYTES (128 * LDS_BYTES)     // 18432

#define OFF_A    0
#define OFF_B0   TILE_BYTES
#define OFF_B1   (2 * TILE_BYTES)
#define OFF_B2   (3 * TILE_BYTES)
#define SMEM_TOTAL (4 * TILE_BYTES)      // 73728 B

#define EXP_SCALE 2.8853900817779268f    // 2*log2(e): exp(2s) = ex2(s*EXP_SCALE)

__device__ __align__(256) uint8_t g_Zf8[TWO_B * D];   // B side: e4m3(z)
__device__ __align__(256) uint8_t g_Zf8s[TWO_B * D];  // A side: e4m3(z * EXP_SCALE)
__device__ float g_pos[BSZ];
__device__ float g_denom[TWO_B];
__device__ unsigned int g_done = 0;

static __device__ __forceinline__ uint32_t smem_u32(const void* p) {
    uint32_t a;
    asm("{ .reg .u64 t; cvta.to.shared.u64 t, %1; cvt.u32.u64 %0, t; }"
        : "=r"(a) : "l"(p));
    return a;
}

#define CP_ASYNC16(dst, src) \
    asm volatile("cp.async.cg.shared.global [%0], [%1], 16;" :: "r"(dst), "l"(src))
#define CP_COMMIT()   asm volatile("cp.async.commit_group;" ::: "memory")
#define CP_WAIT(n)    asm volatile("cp.async.wait_group %0;" :: "n"(n) : "memory")

#define LDM_X4(r0, r1, r2, r3, addr) \
    asm volatile("ldmatrix.sync.aligned.m8n8.x4.shared.b16 {%0,%1,%2,%3}, [%4];" \
                 : "=r"(r0), "=r"(r1), "=r"(r2), "=r"(r3) : "r"(addr))

// fp8 e4m3 MMA: m16n8k32, fp32 accum. Fragment layout == bf16 16816 with
// "b16 element" = 2 packed e4m3 (so ldmatrix.b16 addressing carries over).
#define MMA_FP8(c0, c1, c2, c3, a0, a1, a2, a3, b0, b1) \
    asm volatile("mma.sync.aligned.m16n8k32.row.col.f32.e4m3.e4m3.f32 " \
                 "{%0,%1,%2,%3}, {%4,%5,%6,%7}, {%8,%9}, {%0,%1,%2,%3};" \
                 : "+f"(c0), "+f"(c1), "+f"(c2), "+f"(c3) \
                 : "r"(a0), "r"(a1), "r"(a2), "r"(a3), "r"(b0), "r"(b1))

static __device__ __forceinline__ float ex2f(float x) {
    float r;
    asm("ex2.approx.ftz.f32 %0, %1;" : "=f"(r) : "f"(x));
    return r;
}

static __device__ __forceinline__ uint32_t pack_e4m3x4(float4 v) {
    __nv_fp8x4_e4m3 q(v);
    return *reinterpret_cast<uint32_t*>(&q);
}

// ---------------------------------------------------------------------------
// Kernel 1: normalize; emit e4m3 z (B side) + e4m3 z*EXP_SCALE (A side),
// fp32 positives; zero g_denom.
// ---------------------------------------------------------------------------
__global__ void normalize_kernel(const float* __restrict__ p1,
                                 const float* __restrict__ p2) {
    int gid  = blockIdx.x * blockDim.x + threadIdx.x;
    if (gid < TWO_B) g_denom[gid] = 0.0f;

    int warp = gid >> 5;
    int lane = threadIdx.x & 31;
    if (warp >= BSZ) return;

    float4 a = *(const float4*)&p1[warp * D + lane * 4];
    float4 b = *(const float4*)&p2[warp * D + lane * 4];

    float ss1 = a.x*a.x + a.y*a.y + a.z*a.z + a.w*a.w;
    float ss2 = b.x*b.x + b.y*b.y + b.z*b.z + b.w*b.w;
    #pragma unroll
    for (int o = 16; o > 0; o >>= 1) {
        ss1 += __shfl_xor_sync(0xFFFFFFFFu, ss1, o);
        ss2 += __shfl_xor_sync(0xFFFFFFFFu, ss2, o);
    }
    float r1 = rsqrtf(fmaxf(ss1, 1e-16f));
    float r2 = rsqrtf(fmaxf(ss2, 1e-16f));

    float4 z1 = make_float4(a.x*r1, a.y*r1, a.z*r1, a.w*r1);
    float4 z2 = make_float4(b.x*r2, b.y*r2, b.z*r2, b.w*r2);

    *(uint32_t*)&g_Zf8[warp * D + lane * 4]         = pack_e4m3x4(z1);
    *(uint32_t*)&g_Zf8[(warp + BSZ) * D + lane * 4] = pack_e4m3x4(z2);

    float4 s1 = make_float4(z1.x*EXP_SCALE, z1.y*EXP_SCALE, z1.z*EXP_SCALE, z1.w*EXP_SCALE);
    float4 s2 = make_float4(z2.x*EXP_SCALE, z2.y*EXP_SCALE, z2.z*EXP_SCALE, z2.w*EXP_SCALE);
    *(uint32_t*)&g_Zf8s[warp * D + lane * 4]         = pack_e4m3x4(s1);
    *(uint32_t*)&g_Zf8s[(warp + BSZ) * D + lane * 4] = pack_e4m3x4(s2);

    float d = z1.x*z2.x + z1.y*z2.y + z1.z*z2.z + z1.w*z2.w;
    #pragma unroll
    for (int o = 16; o > 0; o >>= 1)
        d += __shfl_xor_sync(0xFFFFFFFFu, d, o);
    if (lane == 0) g_pos[warp] = d;
}

// one epilogue element e (0..31) of half hf (A pre-scaled: pure MUFU+FADD)
#define EPI_ELEM(hf, e) do {                                                  \
    int mi_ = (e) >> 3, ni_ = (((e) >> 2) & 1), q_ = (e) & 3;                 \
    float ev_ = ex2f(c[mi_][(hf) * 2 + ni_][q_]);                             \
    rowacc[mi_ * 2 + (q_ >> 1)] += ev_;                                       \
    colacc[((hf) * 2 + ni_) * 2 + (q_ & 1)] += ev_;                           \
} while (0)

// ---------------------------------------------------------------------------
// Kernel 2: upper-triangle FP8 QMMA + fused ex2 rowsum/colsum + fused finalize.
// Register-cached A fragments (4ks x 4mi x 4); triple-buffered B; one barrier
// per tile. Same proven R7/R12 schedule (148 CTAs, 14-15 triangle tiles).
// ---------------------------------------------------------------------------
__global__ void __launch_bounds__(NTHREADS, 1) simsum_tri_kernel(float* __restrict__ out) {
    extern __shared__ char smem[];
    const uint32_t sbase = smem_u32(smem);
    const int tid  = threadIdx.x;
    const int lane = tid & 31;
    const int wid  = tid >> 5;
    const int wm = wid >> 2;
    const int wn = wid & 3;
    const int bid = blockIdx.x;

    const int cnt   = 14 + (bid < 8 ? 1 : 0);
    const int start = bid * 14 + (bid < 8 ? bid : 8);

    int r;
    {
        float fr = (129.0f - sqrtf(129.0f * 129.0f - 8.0f * (float)start)) * 0.5f;
        r = (int)fr;
        if (r < 0) r = 0;
        if (r > 63) r = 63;
        while (r < 63 && (r + 1) * (129 - (r + 1)) / 2 <= start) ++r;
        while (r > 0 && r * (129 - r) / 2 > start) --r;
    }
    int j = r + (start - r * (129 - r) / 2);

    const uint32_t a_base = sbase + OFF_A +
        (uint32_t)((wm * 64 + (lane & 15)) * LDS_BYTES + (lane >> 4) * 16);
    const uint32_t b_base_rel =
        (uint32_t)((wn * 32 + (lane & 15)) * LDS_BYTES + (lane >> 4) * 16);
    const int groupid = lane >> 2;
    const uint32_t boff[3] = {OFF_B0, OFF_B1, OFF_B2};

    // prefetch B tile for j into buf 0 (1024 x 16B chunks, FULL tile)
    #pragma unroll
    for (int it = 0; it < 4; ++it) {
        int idx = it * NTHREADS + tid;
        int rr = idx >> 3, cc = idx & 7;
        const char* src = (const char*)(g_Zf8 + (j * 128 + rr) * D + cc * 16);
        CP_ASYNC16(sbase + OFF_B0 + rr * LDS_BYTES + cc * 16, src);
    }
    CP_COMMIT();

    // load A strip r (scaled, full tile), cache fragments in registers
    uint32_t afr[4][4][4];
    {
        #pragma unroll
        for (int it = 0; it < 4; ++it) {
            int idx = it * NTHREADS + tid;
            int rr = idx >> 3, cc = idx & 7;
            uint4 v = *(const uint4*)(g_Zf8s + (r * 128 + rr) * D + cc * 16);
            *(uint4*)(smem + OFF_A + rr * LDS_BYTES + cc * 16) = v;
        }
        __syncthreads();
        #pragma unroll
        for (int ks = 0; ks < 4; ++ks)
            #pragma unroll
            for (int mi = 0; mi < 4; ++mi)
                LDM_X4(afr[ks][mi][0], afr[ks][mi][1], afr[ks][mi][2], afr[ks][mi][3],
                       a_base + (uint32_t)(mi * 16 * LDS_BYTES + ks * 32));
    }

    float rowacc[8];
    #pragma unroll
    for (int i = 0; i < 8; ++i) rowacc[i] = 0.0f;

    int bufsel = 0;
    for (int t = 0; t < cnt; ++t) {
        int rn = r, jn = j + 1;
        if (jn >= NRB) { rn = r + 1; jn = rn; }
        int bufnext = (bufsel == 2) ? 0 : bufsel + 1;

        if (t + 1 < cnt) {
            uint32_t bdst = sbase + boff[bufnext];
            #pragma unroll
            for (int it = 0; it < 4; ++it) {
                int idx = it * NTHREADS + tid;
                int rr = idx >> 3, cc = idx & 7;
                const char* src = (const char*)(g_Zf8 + (jn * 128 + rr) * D + cc * 16);
                CP_ASYNC16(bdst + rr * LDS_BYTES + cc * 16, src);
            }
            CP_COMMIT();
            CP_WAIT(1);
        } else {
            CP_WAIT(0);
        }
        __syncthreads();   // publishes B[t]; guards buf reuse (triple buffer)

        const uint32_t b_base = sbase + boff[bufsel] + b_base_rel;

        float c[4][4][4];
        float colacc[8];
        #pragma unroll
        for (int i = 0; i < 8; ++i) colacc[i] = 0.0f;

        // ---- pass 0: QMMA for ni = 0..1 ----
        #pragma unroll
        for (int mi = 0; mi < 4; ++mi)
            #pragma unroll
            for (int ni = 0; ni < 2; ++ni)
                #pragma unroll
                for (int q = 0; q < 4; ++q) c[mi][ni][q] = 0.0f;
        #pragma unroll
        for (int ks = 0; ks < 4; ++ks) {
            uint32_t b0[4];
            LDM_X4(b0[0], b0[1], b0[2], b0[3], b_base + (uint32_t)(ks * 32));
            #pragma unroll
            for (int mi = 0; mi < 4; ++mi)
                #pragma unroll
                for (int ni = 0; ni < 2; ++ni)
                    MMA_FP8(c[mi][ni][0], c[mi][ni][1], c[mi][ni][2], c[mi][ni][3],
                            afr[ks][mi][0], afr[ks][mi][1], afr[ks][mi][2], afr[ks][mi][3],
                            b0[ni], b0[ni + 2]);
        }

        // ---- pass 1: QMMA for ni = 2..3 with half0 epilogue interleaved ----
        #pragma unroll
        for (int mi = 0; mi < 4; ++mi)
            #pragma unroll
            for (int ni = 2; ni < 4; ++ni)
                #pragma unroll
                for (int q = 0; q < 4; ++q) c[mi][ni][q] = 0.0f;
        #pragma unroll
        for (int ks = 0; ks < 4; ++ks) {
            uint32_t b1[4];
            LDM_X4(b1[0], b1[1], b1[2], b1[3],
                   b_base + (uint32_t)(16 * LDS_BYTES + ks * 32));
            #pragma unroll
            for (int mi = 0; mi < 4; ++mi)
                #pragma unroll
                for (int ni = 0; ni < 2; ++ni)
                    MMA_FP8(c[mi][ni + 2][0], c[mi][ni + 2][1], c[mi][ni + 2][2], c[mi][ni + 2][3],
                            afr[ks][mi][0], afr[ks][mi][1], afr[ks][mi][2], afr[ks][mi][3],
                            b1[ni], b1[ni + 2]);
            // 8 half0 epilogue elements per ks iteration (32 total)
            #pragma unroll
            for (int e8 = 0; e8 < 8; ++e8) EPI_ELEM(0, ks * 8 + e8);
        }

        // ---- half1 epilogue tail ----
        #pragma unroll
        for (int e = 0; e < 32; ++e) EPI_ELEM(1, e);

        // flush colsums unless diagonal tile
        if (j != r) {
            #pragma unroll
            for (int i = 0; i < 8; ++i) {
                colacc[i] += __shfl_xor_sync(0xFFFFFFFFu, colacc[i], 4);
                colacc[i] += __shfl_xor_sync(0xFFFFFFFFu, colacc[i], 8);
                colacc[i] += __shfl_xor_sync(0xFFFFFFFFu, colacc[i], 16);
            }
            if (lane < 4) {
                int cb = j * 128 + wn * 32 + 2 * lane;
                #pragma unroll
                for (int ni = 0; ni < 4; ++ni) {
                    atomicAdd(&g_denom[cb + ni * 8 + 0], colacc[ni * 2 + 0]);
                    atomicAdd(&g_denom[cb + ni * 8 + 1], colacc[ni * 2 + 1]);
                }
            }
        }

        // strip change: flush rowsums, reload A for rn (<=1 per block)
        if (t + 1 < cnt && rn != r) {
            #pragma unroll
            for (int i = 0; i < 8; ++i) {
                rowacc[i] += __shfl_xor_sync(0xFFFFFFFFu, rowacc[i], 1);
                rowacc[i] += __shfl_xor_sync(0xFFFFFFFFu, rowacc[i], 2);
            }
            if ((lane & 3) == 0) {
                int rb = r * 128 + wm * 64 + groupid;
                #pragma unroll
                for (int mi = 0; mi < 4; ++mi) {
                    atomicAdd(&g_denom[rb + mi * 16 + 0], rowacc[mi * 2 + 0]);
                    atomicAdd(&g_denom[rb + mi * 16 + 8], rowacc[mi * 2 + 1]);
                }
            }
            #pragma unroll
            for (int i = 0; i < 8; ++i) rowacc[i] = 0.0f;

            __syncthreads();   // all warps done with prior A-smem reads
            #pragma unroll
            for (int it = 0; it < 4; ++it) {
                int idx = it * NTHREADS + tid;
                int rr = idx >> 3, cc = idx & 7;
                uint4 v = *(const uint4*)(g_Zf8s + (rn * 128 + rr) * D + cc * 16);
                *(uint4*)(smem + OFF_A + rr * LDS_BYTES + cc * 16) = v;
            }
            __syncthreads();
            #pragma unroll
            for (int ks = 0; ks < 4; ++ks)
                #pragma unroll
                for (int mi = 0; mi < 4; ++mi)
                    LDM_X4(afr[ks][mi][0], afr[ks][mi][1], afr[ks][mi][2], afr[ks][mi][3],
                           a_base + (uint32_t)(mi * 16 * LDS_BYTES + ks * 32));
        }

        r = rn; j = jn;
        bufsel = bufnext;
    }

    // final rowsum flush (strip of last processed tile)
    #pragma unroll
    for (int i = 0; i < 8; ++i) {
        rowacc[i] += __shfl_xor_sync(0xFFFFFFFFu, rowacc[i], 1);
        rowacc[i] += __shfl_xor_sync(0xFFFFFFFFu, rowacc[i], 2);
    }
    if ((lane & 3) == 0) {
        int lastidx = start + cnt - 1;
        int rr2;
        {
            float fr = (129.0f - sqrtf(129.0f * 129.0f - 8.0f * (float)lastidx)) * 0.5f;
            rr2 = (int)fr;
            if (rr2 < 0) rr2 = 0;
            if (rr2 > 63) rr2 = 63;
            while (rr2 < 63 && (rr2 + 1) * (129 - (rr2 + 1)) / 2 <= lastidx) ++rr2;
            while (rr2 > 0 && rr2 * (129 - rr2) / 2 > lastidx) --rr2;
        }
        int rb = rr2 * 128 + wm * 64 + groupid;
        #pragma unroll
        for (int mi = 0; mi < 4; ++mi) {
            atomicAdd(&g_denom[rb + mi * 16 + 0], rowacc[mi * 2 + 0]);
            atomicAdd(&g_denom[rb + mi * 16 + 8], rowacc[mi * 2 + 1]);
        }
    }

    // ---- fused finalize: last CTA computes the loss ----
    __shared__ unsigned int s_islast;
    __threadfence();
    __syncthreads();
    if (tid == 0)
        s_islast = (atomicAdd(&g_done, 1u) == NCTAS - 1) ? 1u : 0u;
    __syncthreads();

    if (s_islast) {
        __shared__ float red[NTHREADS];
        float s = 0.0f;
        for (int rr = tid; rr < TWO_B; rr += NTHREADS) {
            float denom = __ldcg(&g_denom[rr]) - 7.3890560989306495f;
            float pos = g_pos[rr & (BSZ - 1)];
            s += __logf(fmaxf(denom, 1e-20f)) - 2.0f * pos;
        }
        red[tid] = s;
        __syncthreads();
        #pragma unroll
        for (int st = NTHREADS / 2; st > 0; st >>= 1) {
            if (tid < st) red[tid] += red[tid + st];
            __syncthreads();
        }
        if (tid == 0) {
            out[0] = red[0] / (float)TWO_B;
            g_done = 0;     // reset for next graph replay
        }
    }
}

// ---------------------------------------------------------------------------
extern "C" void kernel_launch(void* const* d_in, const int* in_sizes, int n_in,
                              void* d_out, int out_size) {
    const float* p1 = (const float*)d_in[0];
    const float* p2 = (const float*)d_in[1];
    float* out = (float*)d_out;
    (void)in_sizes; (void)n_in; (void)out_size;

    cudaFuncSetAttribute(simsum_tri_kernel,
                         cudaFuncAttributeMaxDynamicSharedMemorySize,
                         SMEM_TOTAL);

    normalize_kernel<<<BSZ / 8, 256>>>(p1, p2);
    simsum_tri_kernel<<<NCTAS, NTHREADS, SMEM_TOTAL>>>(out);
}

// round 15
// speedup vs baseline: 1.4709x; 1.4709x over previous
#include <cuda_runtime.h>
#include <cstdint>

#define BSZ 4096
#define D 128
#define TWO_B 8192
#define NRB 64
#define NTHREADS 256
#define NCTAS 148

// s8 tile row: 128 B data + 16 B pad = 144 B (conflict-free banking)
#define LDS_BYTES 144
#define TILE_BYTES (128 * LDS_BYTES)     // 18432

#define OFF_A    0
#define OFF_B0   TILE_BYTES
#define OFF_B1   (2 * TILE_BYTES)
#define OFF_B2   (3 * TILE_BYTES)
#define SMEM_TOTAL (4 * TILE_BYTES)      // 73728 B

#define EXP_SCALE 2.8853900817779268f    // 2*log2(e)
#define QSCALE 127.0f
#define SCALE_COMB (EXP_SCALE / (QSCALE * QSCALE))  // applied in epilogue

__device__ __align__(256) uint8_t g_Zs8[TWO_B * D];  // s8 quantized z (A and B side)
__device__ float g_pos[BSZ];
__device__ float g_denom[TWO_B];
__device__ unsigned int g_done = 0;

static __device__ __forceinline__ uint32_t smem_u32(const void* p) {
    uint32_t a;
    asm("{ .reg .u64 t; cvta.to.shared.u64 t, %1; cvt.u32.u64 %0, t; }"
        : "=r"(a) : "l"(p));
    return a;
}

#define CP_ASYNC16(dst, src) \
    asm volatile("cp.async.cg.shared.global [%0], [%1], 16;" :: "r"(dst), "l"(src))
#define CP_COMMIT()   asm volatile("cp.async.commit_group;" ::: "memory")
#define CP_WAIT(n)    asm volatile("cp.async.wait_group %0;" :: "n"(n) : "memory")

#define LDM_X4(r0, r1, r2, r3, addr) \
    asm volatile("ldmatrix.sync.aligned.m8n8.x4.shared.b16 {%0,%1,%2,%3}, [%4];" \
                 : "=r"(r0), "=r"(r1), "=r"(r2), "=r"(r3) : "r"(addr))

// int8 IMMA: m16n8k32, s32 accum (native since Turing; 2x bf16 MAC/instr).
// Fragment byte-layout identical to the (correctness-proven) fp8 k32 variant.
#define MMA_S8(c0, c1, c2, c3, a0, a1, a2, a3, b0, b1) \
    asm volatile("mma.sync.aligned.m16n8k32.row.col.s32.s8.s8.s32 " \
                 "{%0,%1,%2,%3}, {%4,%5,%6,%7}, {%8,%9}, {%0,%1,%2,%3};" \
                 : "+r"(c0), "+r"(c1), "+r"(c2), "+r"(c3) \
                 : "r"(a0), "r"(a1), "r"(a2), "r"(a3), "r"(b0), "r"(b1))

static __device__ __forceinline__ float ex2f(float x) {
    float r;
    asm("ex2.approx.ftz.f32 %0, %1;" : "=f"(r) : "f"(x));
    return r;
}

static __device__ __forceinline__ uint32_t pack_s8x4(float4 v) {
    int a = __float2int_rn(v.x * QSCALE);
    int b = __float2int_rn(v.y * QSCALE);
    int c = __float2int_rn(v.z * QSCALE);
    int d = __float2int_rn(v.w * QSCALE);
    return (uint32_t)(a & 0xff) | ((uint32_t)(b & 0xff) << 8) |
           ((uint32_t)(c & 0xff) << 16) | ((uint32_t)(d & 0xff) << 24);
}

// ---------------------------------------------------------------------------
// Kernel 1: normalize; emit s8 z; fp32 positives; zero g_denom.
// ---------------------------------------------------------------------------
__global__ void normalize_kernel(const float* __restrict__ p1,
                                 const float* __restrict__ p2) {
    int gid  = blockIdx.x * blockDim.x + threadIdx.x;
    if (gid < TWO_B) g_denom[gid] = 0.0f;

    int warp = gid >> 5;
    int lane = threadIdx.x & 31;
    if (warp >= BSZ) return;

    float4 a = *(const float4*)&p1[warp * D + lane * 4];
    float4 b = *(const float4*)&p2[warp * D + lane * 4];

    float ss1 = a.x*a.x + a.y*a.y + a.z*a.z + a.w*a.w;
    float ss2 = b.x*b.x + b.y*b.y + b.z*b.z + b.w*b.w;
    #pragma unroll
    for (int o = 16; o > 0; o >>= 1) {
        ss1 += __shfl_xor_sync(0xFFFFFFFFu, ss1, o);
        ss2 += __shfl_xor_sync(0xFFFFFFFFu, ss2, o);
    }
    float r1 = rsqrtf(fmaxf(ss1, 1e-16f));
    float r2 = rsqrtf(fmaxf(ss2, 1e-16f));

    float4 z1 = make_float4(a.x*r1, a.y*r1, a.z*r1, a.w*r1);
    float4 z2 = make_float4(b.x*r2, b.y*r2, b.z*r2, b.w*r2);

    *(uint32_t*)&g_Zs8[warp * D + lane * 4]         = pack_s8x4(z1);
    *(uint32_t*)&g_Zs8[(warp + BSZ) * D + lane * 4] = pack_s8x4(z2);

    float d = z1.x*z2.x + z1.y*z2.y + z1.z*z2.z + z1.w*z2.w;
    #pragma unroll
    for (int o = 16; o > 0; o >>= 1)
        d += __shfl_xor_sync(0xFFFFFFFFu, d, o);
    if (lane == 0) g_pos[warp] = d;
}

// one epilogue element e (0..31) of half hf: I2F + FMUL + ex2 (+2 FADD)
#define EPI_ELEM(hf, e) do {                                                  \
    int mi_ = (e) >> 3, ni_ = (((e) >> 2) & 1), q_ = (e) & 3;                 \
    float ev_ = ex2f(__int2float_rn(c[mi_][(hf) * 2 + ni_][q_]) * SCALE_COMB);\
    rowacc[mi_ * 2 + (q_ >> 1)] += ev_;                                       \
    colacc[((hf) * 2 + ni_) * 2 + (q_ & 1)] += ev_;                           \
} while (0)

// ---------------------------------------------------------------------------
// Kernel 2: upper-triangle s8 IMMA + fused ex2 rowsum/colsum + fused finalize.
// Register-cached A fragments (4ks x 4mi x 4); triple-buffered B; one barrier
// per tile. Proven R12/R14 schedule (148 CTAs, 14-15 triangle tiles).
// ---------------------------------------------------------------------------
__global__ void __launch_bounds__(NTHREADS, 1) simsum_tri_kernel(float* __restrict__ out) {
    extern __shared__ char smem[];
    const uint32_t sbase = smem_u32(smem);
    const int tid  = threadIdx.x;
    const int lane = tid & 31;
    const int wid  = tid >> 5;
    const int wm = wid >> 2;
    const int wn = wid & 3;
    const int bid = blockIdx.x;

    const int cnt   = 14 + (bid < 8 ? 1 : 0);
    const int start = bid * 14 + (bid < 8 ? bid : 8);

    int r;
    {
        float fr = (129.0f - sqrtf(129.0f * 129.0f - 8.0f * (float)start)) * 0.5f;
        r = (int)fr;
        if (r < 0) r = 0;
        if (r > 63) r = 63;
        while (r < 63 && (r + 1) * (129 - (r + 1)) / 2 <= start) ++r;
        while (r > 0 && r * (129 - r) / 2 > start) --r;
    }
    int j = r + (start - r * (129 - r) / 2);

    const uint32_t a_base = sbase + OFF_A +
        (uint32_t)((wm * 64 + (lane & 15)) * LDS_BYTES + (lane >> 4) * 16);
    const uint32_t b_base_rel =
        (uint32_t)((wn * 32 + (lane & 15)) * LDS_BYTES + (lane >> 4) * 16);
    const int groupid = lane >> 2;
    const uint32_t boff[3] = {OFF_B0, OFF_B1, OFF_B2};

    // prefetch B tile for j into buf 0 (1024 x 16B chunks, full tile)
    #pragma unroll
    for (int it = 0; it < 4; ++it) {
        int idx = it * NTHREADS + tid;
        int rr = idx >> 3, cc = idx & 7;
        const char* src = (const char*)(g_Zs8 + (j * 128 + rr) * D + cc * 16);
        CP_ASYNC16(sbase + OFF_B0 + rr * LDS_BYTES + cc * 16, src);
    }
    CP_COMMIT();

    // load A strip r (full tile), cache fragments in registers
    uint32_t afr[4][4][4];
    {
        #pragma unroll
        for (int it = 0; it < 4; ++it) {
            int idx = it * NTHREADS + tid;
            int rr = idx >> 3, cc = idx & 7;
            uint4 v = *(const uint4*)(g_Zs8 + (r * 128 + rr) * D + cc * 16);
            *(uint4*)(smem + OFF_A + rr * LDS_BYTES + cc * 16) = v;
        }
        __syncthreads();
        #pragma unroll
        for (int ks = 0; ks < 4; ++ks)
            #pragma unroll
            for (int mi = 0; mi < 4; ++mi)
                LDM_X4(afr[ks][mi][0], afr[ks][mi][1], afr[ks][mi][2], afr[ks][mi][3],
                       a_base + (uint32_t)(mi * 16 * LDS_BYTES + ks * 32));
    }

    float rowacc[8];
    #pragma unroll
    for (int i = 0; i < 8; ++i) rowacc[i] = 0.0f;

    int bufsel = 0;
    for (int t = 0; t < cnt; ++t) {
        int rn = r, jn = j + 1;
        if (jn >= NRB) { rn = r + 1; jn = rn; }
        int bufnext = (bufsel == 2) ? 0 : bufsel + 1;

        if (t + 1 < cnt) {
            uint32_t bdst = sbase + boff[bufnext];
            #pragma unroll
            for (int it = 0; it < 4; ++it) {
                int idx = it * NTHREADS + tid;
                int rr = idx >> 3, cc = idx & 7;
                const char* src = (const char*)(g_Zs8 + (jn * 128 + rr) * D + cc * 16);
                CP_ASYNC16(bdst + rr * LDS_BYTES + cc * 16, src);
            }
            CP_COMMIT();
            CP_WAIT(1);
        } else {
            CP_WAIT(0);
        }
        __syncthreads();   // publishes B[t]; guards buf reuse (triple buffer)

        const uint32_t b_base = sbase + boff[bufsel] + b_base_rel;

        int c[4][4][4];
        float colacc[8];
        #pragma unroll
        for (int i = 0; i < 8; ++i) colacc[i] = 0.0f;

        // ---- pass 0: IMMA for ni = 0..1 ----
        #pragma unroll
        for (int mi = 0; mi < 4; ++mi)
            #pragma unroll
            for (int ni = 0; ni < 2; ++ni)
                #pragma unroll
                for (int q = 0; q < 4; ++q) c[mi][ni][q] = 0;
        #pragma unroll
        for (int ks = 0; ks < 4; ++ks) {
            uint32_t b0[4];
            LDM_X4(b0[0], b0[1], b0[2], b0[3], b_base + (uint32_t)(ks * 32));
            #pragma unroll
            for (int mi = 0; mi < 4; ++mi)
                #pragma unroll
                for (int ni = 0; ni < 2; ++ni)
                    MMA_S8(c[mi][ni][0], c[mi][ni][1], c[mi][ni][2], c[mi][ni][3],
                           afr[ks][mi][0], afr[ks][mi][1], afr[ks][mi][2], afr[ks][mi][3],
                           b0[ni], b0[ni + 2]);
        }

        // ---- pass 1: IMMA for ni = 2..3 with half0 epilogue interleaved ----
        #pragma unroll
        for (int mi = 0; mi < 4; ++mi)
            #pragma unroll
            for (int ni = 2; ni < 4; ++ni)
                #pragma unroll
                for (int q = 0; q < 4; ++q) c[mi][ni][q] = 0;
        #pragma unroll
        for (int ks = 0; ks < 4; ++ks) {
            uint32_t b1[4];
            LDM_X4(b1[0], b1[1], b1[2], b1[3],
                   b_base + (uint32_t)(16 * LDS_BYTES + ks * 32));
            #pragma unroll
            for (int mi = 0; mi < 4; ++mi)
                #pragma unroll
                for (int ni = 0; ni < 2; ++ni)
                    MMA_S8(c[mi][ni + 2][0], c[mi][ni + 2][1], c[mi][ni + 2][2], c[mi][ni + 2][3],
                           afr[ks][mi][0], afr[ks][mi][1], afr[ks][mi][2], afr[ks][mi][3],
                           b1[ni], b1[ni + 2]);
            #pragma unroll
            for (int e8 = 0; e8 < 8; ++e8) EPI_ELEM(0, ks * 8 + e8);
        }

        // ---- half1 epilogue tail ----
        #pragma unroll
        for (int e = 0; e < 32; ++e) EPI_ELEM(1, e);

        // flush colsums unless diagonal tile
        if (j != r) {
            #pragma unroll
            for (int i = 0; i < 8; ++i) {
                colacc[i] += __shfl_xor_sync(0xFFFFFFFFu, colacc[i], 4);
                colacc[i] += __shfl_xor_sync(0xFFFFFFFFu, colacc[i], 8);
                colacc[i] += __shfl_xor_sync(0xFFFFFFFFu, colacc[i], 16);
            }
            if (lane < 4) {
                int cb = j * 128 + wn * 32 + 2 * lane;
                #pragma unroll
                for (int ni = 0; ni < 4; ++ni) {
                    atomicAdd(&g_denom[cb + ni * 8 + 0], colacc[ni * 2 + 0]);
                    atomicAdd(&g_denom[cb + ni * 8 + 1], colacc[ni * 2 + 1]);
                }
            }
        }

        // strip change: flush rowsums, reload A for rn (<=1 per block)
        if (t + 1 < cnt && rn != r) {
            #pragma unroll
            for (int i = 0; i < 8; ++i) {
                rowacc[i] += __shfl_xor_sync(0xFFFFFFFFu, rowacc[i], 1);
                rowacc[i] += __shfl_xor_sync(0xFFFFFFFFu, rowacc[i], 2);
            }
            if ((lane & 3) == 0) {
                int rb = r * 128 + wm * 64 + groupid;
                #pragma unroll
                for (int mi = 0; mi < 4; ++mi) {
                    atomicAdd(&g_denom[rb + mi * 16 + 0], rowacc[mi * 2 + 0]);
                    atomicAdd(&g_denom[rb + mi * 16 + 8], rowacc[mi * 2 + 1]);
                }
            }
            #pragma unroll
            for (int i = 0; i < 8; ++i) rowacc[i] = 0.0f;

            __syncthreads();   // all warps done with prior A-smem reads
            #pragma unroll
            for (int it = 0; it < 4; ++it) {
                int idx = it * NTHREADS + tid;
                int rr = idx >> 3, cc = idx & 7;
                uint4 v = *(const uint4*)(g_Zs8 + (rn * 128 + rr) * D + cc * 16);
                *(uint4*)(smem + OFF_A + rr * LDS_BYTES + cc * 16) = v;
            }
            __syncthreads();
            #pragma unroll
            for (int ks = 0; ks < 4; ++ks)
                #pragma unroll
                for (int mi = 0; mi < 4; ++mi)
                    LDM_X4(afr[ks][mi][0], afr[ks][mi][1], afr[ks][mi][2], afr[ks][mi][3],
                           a_base + (uint32_t)(mi * 16 * LDS_BYTES + ks * 32));
        }

        r = rn; j = jn;
        bufsel = bufnext;
    }

    // final rowsum flush (strip of last processed tile)
    #pragma unroll
    for (int i = 0; i < 8; ++i) {
        rowacc[i] += __shfl_xor_sync(0xFFFFFFFFu, rowacc[i], 1);
        rowacc[i] += __shfl_xor_sync(0xFFFFFFFFu, rowacc[i], 2);
    }
    if ((lane & 3) == 0) {
        int lastidx = start + cnt - 1;
        int rr2;
        {
            float fr = (129.0f - sqrtf(129.0f * 129.0f - 8.0f * (float)lastidx)) * 0.5f;
            rr2 = (int)fr;
            if (rr2 < 0) rr2 = 0;
            if (rr2 > 63) rr2 = 63;
            while (rr2 < 63 && (rr2 + 1) * (129 - (rr2 + 1)) / 2 <= lastidx) ++rr2;
            while (rr2 > 0 && rr2 * (129 - rr2) / 2 > lastidx) --rr2;
        }
        int rb = rr2 * 128 + wm * 64 + groupid;
        #pragma unroll
        for (int mi = 0; mi < 4; ++mi) {
            atomicAdd(&g_denom[rb + mi * 16 + 0], rowacc[mi * 2 + 0]);
            atomicAdd(&g_denom[rb + mi * 16 + 8], rowacc[mi * 2 + 1]);
        }
    }

    // ---- fused finalize: last CTA computes the loss ----
    __shared__ unsigned int s_islast;
    __threadfence();
    __syncthreads();
    if (tid == 0)
        s_islast = (atomicAdd(&g_done, 1u) == NCTAS - 1) ? 1u : 0u;
    __syncthreads();

    if (s_islast) {
        __shared__ float red[NTHREADS];
        float s = 0.0f;
        for (int rr = tid; rr < TWO_B; rr += NTHREADS) {
            float denom = __ldcg(&g_denom[rr]) - 7.3890560989306495f;
            float pos = g_pos[rr & (BSZ - 1)];
            s += __logf(fmaxf(denom, 1e-20f)) - 2.0f * pos;
        }
        red[tid] = s;
        __syncthreads();
        #pragma unroll
        for (int st = NTHREADS / 2; st > 0; st >>= 1) {
            if (tid < st) red[tid] += red[tid + st];
            __syncthreads();
        }
        if (tid == 0) {
            out[0] = red[0] / (float)TWO_B;
            g_done = 0;     // reset for next graph replay
        }
    }
}

// ---------------------------------------------------------------------------
extern "C" void kernel_launch(void* const* d_in, const int* in_sizes, int n_in,
                              void* d_out, int out_size) {
    const float* p1 = (const float*)d_in[0];
    const float* p2 = (const float*)d_in[1];
    float* out = (float*)d_out;
    (void)in_sizes; (void)n_in; (void)out_size;

    cudaFuncSetAttribute(simsum_tri_kernel,
                         cudaFuncAttributeMaxDynamicSharedMemorySize,
                         SMEM_TOTAL);

    normalize_kernel<<<BSZ / 8, 256>>>(p1, p2);
    simsum_tri_kernel<<<NCTAS, NTHREADS, SMEM_TOTAL>>>(out);
}

// round 16
// speedup vs baseline: 1.6308x; 1.1087x over previous
#include <cuda_runtime.h>
#include <cstdint>

#define BSZ 4096
#define D 128
#define TWO_B 8192
#define NRB 64
#define NTHREADS 256
#define NCTAS 288                       // sum_r ceil((64-r)/8); 2 CTAs/SM

// s8 tile row: 128 B data + 16 B pad = 144 B (conflict-free banking)
#define LDS_BYTES 144
#define TILE_BYTES (128 * LDS_BYTES)    // 18432

#define OFF_A    0
#define OFF_B0   TILE_BYTES
#define OFF_B1   (2 * TILE_BYTES)
#define OFF_B2   (3 * TILE_BYTES)
#define SMEM_TOTAL (4 * TILE_BYTES)     // 73728 B -> 2 CTAs/SM (147456 < 228K)

#define EXP_SCALE 2.8853900817779268f   // 2*log2(e)
#define QSCALE 127.0f
#define SCALE_COMB (EXP_SCALE / (QSCALE * QSCALE))

__device__ __align__(256) uint8_t g_Zs8[TWO_B * D];
__device__ float g_pos[BSZ];
__device__ float g_denom[TWO_B];
__device__ unsigned int g_done = 0;

static __device__ __forceinline__ uint32_t smem_u32(const void* p) {
    uint32_t a;
    asm("{ .reg .u64 t; cvta.to.shared.u64 t, %1; cvt.u32.u64 %0, t; }"
        : "=r"(a) : "l"(p));
    return a;
}

#define CP_ASYNC16(dst, src) \
    asm volatile("cp.async.cg.shared.global [%0], [%1], 16;" :: "r"(dst), "l"(src))
#define CP_COMMIT()   asm volatile("cp.async.commit_group;" ::: "memory")
#define CP_WAIT(n)    asm volatile("cp.async.wait_group %0;" :: "n"(n) : "memory")

#define LDM_X4(r0, r1, r2, r3, addr) \
    asm volatile("ldmatrix.sync.aligned.m8n8.x4.shared.b16 {%0,%1,%2,%3}, [%4];" \
                 : "=r"(r0), "=r"(r1), "=r"(r2), "=r"(r3) : "r"(addr))

#define MMA_S8(c0, c1, c2, c3, a0, a1, a2, a3, b0, b1) \
    asm volatile("mma.sync.aligned.m16n8k32.row.col.s32.s8.s8.s32 " \
                 "{%0,%1,%2,%3}, {%4,%5,%6,%7}, {%8,%9}, {%0,%1,%2,%3};" \
                 : "+r"(c0), "+r"(c1), "+r"(c2), "+r"(c3) \
                 : "r"(a0), "r"(a1), "r"(a2), "r"(a3), "r"(b0), "r"(b1))

static __device__ __forceinline__ float ex2f(float x) {
    float r;
    asm("ex2.approx.ftz.f32 %0, %1;" : "=f"(r) : "f"(x));
    return r;
}

static __device__ __forceinline__ uint32_t pack_s8x4(float4 v) {
    int a = __float2int_rn(v.x * QSCALE);
    int b = __float2int_rn(v.y * QSCALE);
    int c = __float2int_rn(v.z * QSCALE);
    int d = __float2int_rn(v.w * QSCALE);
    return (uint32_t)(a & 0xff) | ((uint32_t)(b & 0xff) << 8) |
           ((uint32_t)(c & 0xff) << 16) | ((uint32_t)(d & 0xff) << 24);
}

// ---------------------------------------------------------------------------
// Kernel 1: normalize; emit s8 z; fp32 positives; zero g_denom.
// ---------------------------------------------------------------------------
__global__ void normalize_kernel(const float* __restrict__ p1,
                                 const float* __restrict__ p2) {
    int gid  = blockIdx.x * blockDim.x + threadIdx.x;
    if (gid < TWO_B) g_denom[gid] = 0.0f;

    int warp = gid >> 5;
    int lane = threadIdx.x & 31;
    if (warp >= BSZ) return;

    float4 a = *(const float4*)&p1[warp * D + lane * 4];
    float4 b = *(const float4*)&p2[warp * D + lane * 4];

    float ss1 = a.x*a.x + a.y*a.y + a.z*a.z + a.w*a.w;
    float ss2 = b.x*b.x + b.y*b.y + b.z*b.z + b.w*b.w;
    #pragma unroll
    for (int o = 16; o > 0; o >>= 1) {
        ss1 += __shfl_xor_sync(0xFFFFFFFFu, ss1, o);
        ss2 += __shfl_xor_sync(0xFFFFFFFFu, ss2, o);
    }
    float r1 = rsqrtf(fmaxf(ss1, 1e-16f));
    float r2 = rsqrtf(fmaxf(ss2, 1e-16f));

    float4 z1 = make_float4(a.x*r1, a.y*r1, a.z*r1, a.w*r1);
    float4 z2 = make_float4(b.x*r2, b.y*r2, b.z*r2, b.w*r2);

    *(uint32_t*)&g_Zs8[warp * D + lane * 4]         = pack_s8x4(z1);
    *(uint32_t*)&g_Zs8[(warp + BSZ) * D + lane * 4] = pack_s8x4(z2);

    float d = z1.x*z2.x + z1.y*z2.y + z1.z*z2.z + z1.w*z2.w;
    #pragma unroll
    for (int o = 16; o > 0; o >>= 1)
        d += __shfl_xor_sync(0xFFFFFFFFu, d, o);
    if (lane == 0) g_pos[warp] = d;
}

// one epilogue element e (0..31) of half hf; c is int c[4][2][4]
#define EPI_ELEM(hf, e) do {                                                  \
    int mi_ = (e) >> 3, ni_ = (((e) >> 2) & 1), q_ = (e) & 3;                 \
    float ev_ = ex2f(__int2float_rn(c[mi_][ni_][q_]) * SCALE_COMB);           \
    rowacc[mi_ * 2 + (q_ >> 1)] += ev_;                                       \
    colacc[((hf) * 2 + ni_) * 2 + (q_ & 1)] += ev_;                           \
} while (0)

// ---------------------------------------------------------------------------
// Kernel 2: upper-triangle s8 IMMA + fused ex2 rowsum/colsum + fused finalize.
// 2 CTAs/SM (regs <= 128): c accums halved (sequential N-halves), afr cached
// for mi 0..1 only (mi 2..3 re-ldmatrix'd per ks). R11's proven single-strip
// chunk schedule (288 blocks); triple-buffered B; one barrier per tile.
// ---------------------------------------------------------------------------
__global__ void __launch_bounds__(NTHREADS, 2) simsum_tri_kernel(float* __restrict__ out) {
    extern __shared__ char smem[];
    const uint32_t sbase = smem_u32(smem);
    const int tid  = threadIdx.x;
    const int lane = tid & 31;
    const int wid  = tid >> 5;
    const int wm = wid >> 2;
    const int wn = wid & 3;

    // block -> (strip r, chunk) via integer scan (proven in R11)
    int b = blockIdx.x;
    int r = 0;
    #pragma unroll 1
    for (;;) {
        int nch = (NRB - r + 7) >> 3;
        if (b < nch) break;
        b -= nch;
        ++r;
    }
    const int j0  = r + b * 8;
    const int cnt = min(8, NRB - j0);

    const uint32_t a_base = sbase + OFF_A +
        (uint32_t)((wm * 64 + (lane & 15)) * LDS_BYTES + (lane >> 4) * 16);
    const uint32_t b_base_rel =
        (uint32_t)((wn * 32 + (lane & 15)) * LDS_BYTES + (lane >> 4) * 16);
    const int groupid = lane >> 2;
    const uint32_t boff[3] = {OFF_B0, OFF_B1, OFF_B2};

    // prefetch B tile for j0 into buf 0 (1024 x 16B chunks, full tile)
    #pragma unroll
    for (int it = 0; it < 4; ++it) {
        int idx = it * NTHREADS + tid;
        int rr = idx >> 3, cc = idx & 7;
        const char* src = (const char*)(g_Zs8 + (j0 * 128 + rr) * D + cc * 16);
        CP_ASYNC16(sbase + OFF_B0 + rr * LDS_BYTES + cc * 16, src);
    }
    CP_COMMIT();

    // load A strip r into smem (full tile, once per block)
    #pragma unroll
    for (int it = 0; it < 4; ++it) {
        int idx = it * NTHREADS + tid;
        int rr = idx >> 3, cc = idx & 7;
        uint4 v = *(const uint4*)(g_Zs8 + (r * 128 + rr) * D + cc * 16);
        *(uint4*)(smem + OFF_A + rr * LDS_BYTES + cc * 16) = v;
    }
    __syncthreads();

    // cache A fragments for mi = 0..1 only (32 regs)
    uint32_t afr[4][2][4];
    #pragma unroll
    for (int ks = 0; ks < 4; ++ks)
        #pragma unroll
        for (int mi = 0; mi < 2; ++mi)
            LDM_X4(afr[ks][mi][0], afr[ks][mi][1], afr[ks][mi][2], afr[ks][mi][3],
                   a_base + (uint32_t)(mi * 16 * LDS_BYTES + ks * 32));

    float rowacc[8];
    #pragma unroll
    for (int i = 0; i < 8; ++i) rowacc[i] = 0.0f;

    int bufsel = 0;
    for (int t = 0; t < cnt; ++t) {
        const int j = j0 + t;
        int bufnext = (bufsel == 2) ? 0 : bufsel + 1;

        if (t + 1 < cnt) {
            uint32_t bdst = sbase + boff[bufnext];
            #pragma unroll
            for (int it = 0; it < 4; ++it) {
                int idx = it * NTHREADS + tid;
                int rr = idx >> 3, cc = idx & 7;
                const char* src = (const char*)(g_Zs8 + ((j + 1) * 128 + rr) * D + cc * 16);
                CP_ASYNC16(bdst + rr * LDS_BYTES + cc * 16, src);
            }
            CP_COMMIT();
            CP_WAIT(1);
        } else {
            CP_WAIT(0);
        }
        __syncthreads();   // publishes B[t]; guards buf reuse (triple buffer)

        const uint32_t b_base = sbase + boff[bufsel] + b_base_rel;

        float colacc[8];
        #pragma unroll
        for (int i = 0; i < 8; ++i) colacc[i] = 0.0f;

        // ---- sequential N-halves: 32 int accums live at a time ----
        #pragma unroll
        for (int h = 0; h < 2; ++h) {
            int c[4][2][4];
            #pragma unroll
            for (int mi = 0; mi < 4; ++mi)
                #pragma unroll
                for (int ni = 0; ni < 2; ++ni)
                    #pragma unroll
                    for (int q = 0; q < 4; ++q) c[mi][ni][q] = 0;

            #pragma unroll
            for (int ks = 0; ks < 4; ++ks) {
                uint32_t bb[4];
                LDM_X4(bb[0], bb[1], bb[2], bb[3],
                       b_base + (uint32_t)(h * 16 * LDS_BYTES + ks * 32));
                uint32_t ah[2][4];
                LDM_X4(ah[0][0], ah[0][1], ah[0][2], ah[0][3],
                       a_base + (uint32_t)(2 * 16 * LDS_BYTES + ks * 32));
                LDM_X4(ah[1][0], ah[1][1], ah[1][2], ah[1][3],
                       a_base + (uint32_t)(3 * 16 * LDS_BYTES + ks * 32));
                #pragma unroll
                for (int mi = 0; mi < 2; ++mi)
                    #pragma unroll
                    for (int ni = 0; ni < 2; ++ni)
                        MMA_S8(c[mi][ni][0], c[mi][ni][1], c[mi][ni][2], c[mi][ni][3],
                               afr[ks][mi][0], afr[ks][mi][1], afr[ks][mi][2], afr[ks][mi][3],
                               bb[ni], bb[ni + 2]);
                #pragma unroll
                for (int mi = 0; mi < 2; ++mi)
                    #pragma unroll
                    for (int ni = 0; ni < 2; ++ni)
                        MMA_S8(c[mi + 2][ni][0], c[mi + 2][ni][1], c[mi + 2][ni][2], c[mi + 2][ni][3],
                               ah[mi][0], ah[mi][1], ah[mi][2], ah[mi][3],
                               bb[ni], bb[ni + 2]);
            }

            // epilogue for this half (32 elems)
            #pragma unroll
            for (int e = 0; e < 32; ++e) EPI_ELEM(h, e);
        }

        // flush colsums unless diagonal tile
        if (j != r) {
            #pragma unroll
            for (int i = 0; i < 8; ++i) {
                colacc[i] += __shfl_xor_sync(0xFFFFFFFFu, colacc[i], 4);
                colacc[i] += __shfl_xor_sync(0xFFFFFFFFu, colacc[i], 8);
                colacc[i] += __shfl_xor_sync(0xFFFFFFFFu, colacc[i], 16);
            }
            if (lane < 4) {
                int cb = j * 128 + wn * 32 + 2 * lane;
                #pragma unroll
                for (int ni = 0; ni < 4; ++ni) {
                    atomicAdd(&g_denom[cb + ni * 8 + 0], colacc[ni * 2 + 0]);
                    atomicAdd(&g_denom[cb + ni * 8 + 1], colacc[ni * 2 + 1]);
                }
            }
        }

        bufsel = bufnext;
    }

    // rowsum flush (single strip r for the whole block)
    #pragma unroll
    for (int i = 0; i < 8; ++i) {
        rowacc[i] += __shfl_xor_sync(0xFFFFFFFFu, rowacc[i], 1);
        rowacc[i] += __shfl_xor_sync(0xFFFFFFFFu, rowacc[i], 2);
    }
    if ((lane & 3) == 0) {
        int rb = r * 128 + wm * 64 + groupid;
        #pragma unroll
        for (int mi = 0; mi < 4; ++mi) {
            atomicAdd(&g_denom[rb + mi * 16 + 0], rowacc[mi * 2 + 0]);
            atomicAdd(&g_denom[rb + mi * 16 + 8], rowacc[mi * 2 + 1]);
        }
    }

    // ---- fused finalize: last CTA computes the loss ----
    __shared__ unsigned int s_islast;
    __threadfence();
    __syncthreads();
    if (tid == 0)
        s_islast = (atomicAdd(&g_done, 1u) == NCTAS - 1) ? 1u : 0u;
    __syncthreads();

    if (s_islast) {
        __shared__ float red[NTHREADS];
        float s = 0.0f;
        for (int rr = tid; rr < TWO_B; rr += NTHREADS) {
            float denom = __ldcg(&g_denom[rr]) - 7.3890560989306495f;
            float pos = g_pos[rr & (BSZ - 1)];
            s += __logf(fmaxf(denom, 1e-20f)) - 2.0f * pos;
        }
        red[tid] = s;
        __syncthreads();
        #pragma unroll
        for (int st = NTHREADS / 2; st > 0; st >>= 1) {
            if (tid < st) red[tid] += red[tid + st];
            __syncthreads();
        }
        if (tid == 0) {
            out[0] = red[0] / (float)TWO_B;
            g_done = 0;     // reset for next graph replay
        }
    }
}

// ---------------------------------------------------------------------------
extern "C" void kernel_launch(void* const* d_in, const int* in_sizes, int n_in,
                              void* d_out, int out_size) {
    const float* p1 = (const float*)d_in[0];
    const float* p2 = (const float*)d_in[1];
    float* out = (float*)d_out;
    (void)in_sizes; (void)n_in; (void)out_size;

    cudaFuncSetAttribute(simsum_tri_kernel,
                         cudaFuncAttributeMaxDynamicSharedMemorySize,
                         SMEM_TOTAL);

    normalize_kernel<<<BSZ / 8, 256>>>(p1, p2);
    simsum_tri_kernel<<<NCTAS, NTHREADS, SMEM_TOTAL>>>(out);
}